// round 4
// baseline (speedup 1.0000x reference)
#include <cuda_runtime.h>

// Problem constants
#define NB 2
#define NC 128
#define NS 16384        // T*H*W = 4*64*64
#define NN 1024         // patch tokens: 4*16*16
#define NP 16           // pixels per patch
#define NG 32           // heads == groupnorm groups
#define TBL 6727        // (2T-1)*(2h-1)*(2w-1) = 7*31*31
#define EPS 1e-5f

typedef unsigned long long ull;

// Scratch (static device memory; no allocations)
__device__ float g_y[3][NB][NC][NN][NP];       // raw projections, patch layout (~50MB)
__device__ float g_part[3][NB][NG][256][2];    // per-sTile partial (sum, sumsq)
__device__ float g_cscale[3][NB][NC];          // GN folded: scale = gamma*rstd
__device__ float g_cshift[3][NB][NC];          // GN folded: shift = beta - mu*scale
__device__ float g_qp[NB][NG][4][NN];          // pooled normalized q (pre-scaled 1/sqrt(d))
__device__ float g_kp[NB][NG][4][NN];          // pooled normalized k

// Packed f32x2 FMA (2x fp32 throughput per issue slot)
static __device__ __forceinline__ ull fma2(ull a, ull b, ull c) {
  ull d;
  asm("fma.rn.f32x2 %0, %1, %2, %3;" : "=l"(d) : "l"(a), "l"(b), "l"(c));
  return d;
}
static __device__ __forceinline__ float2 ull2f2(ull u) {
  float2 f;
  f.x = __uint_as_float((unsigned)u);
  f.y = __uint_as_float((unsigned)(u >> 32));
  return f;
}

// ---------------------------------------------------------------------------
// K1: projections with fma.rn.f32x2. Y[o,s] = sum_c W[o,c]*x[c,s].
// W staged DUPLICATED ({w,w}) in smem so fma2 needs no packing.
// Thread: 4 o x 4 s (2 f32x2 pairs over s).
// ---------------------------------------------------------------------------
__global__ void __launch_bounds__(256) proj_kernel(
    const float* __restrict__ x, const float* __restrict__ Wq,
    const float* __restrict__ Wk, const float* __restrict__ Wv) {
  const int sTile = blockIdx.x;          // 0..255
  const int oTile = blockIdx.y;          // 0..1
  const int proj = blockIdx.z >> 1;      // 0..2
  const int b = blockIdx.z & 1;
  const float* __restrict__ W = (proj == 0) ? Wq : ((proj == 1) ? Wk : Wv);

  __shared__ ull   W2[32][66];           // duplicated {w,w}: [k][o_local]
  __shared__ float Xsh[32][64];          // [k][s_local]
  __shared__ float redS[16][17];
  __shared__ float redQ[16][17];

  const int tid = threadIdx.x;
  const int oq = tid >> 4;               // 0..15
  const int sq = tid & 15;               // 0..15
  const int sl0 = sq * 4;
  const int s0 = sTile * 64 + sl0;

  ull acc[4][2];
#pragma unroll
  for (int i = 0; i < 4; i++) { acc[i][0] = 0ull; acc[i][1] = 0ull; }

  const float* __restrict__ xb = x + (size_t)b * NC * NS;

  for (int kc = 0; kc < 128; kc += 32) {
    __syncthreads();
#pragma unroll
    for (int i = tid; i < 2048; i += 256) {
      int ol = i >> 5, kk = i & 31;
      float w = W[(oTile * 64 + ol) * 128 + kc + kk];
      *(float2*)&W2[kk][ol] = make_float2(w, w);
    }
#pragma unroll
    for (int i = tid; i < 2048; i += 256) {
      int kk = i >> 6, ss = i & 63;
      Xsh[kk][ss] = xb[(size_t)(kc + kk) * NS + sTile * 64 + ss];
    }
    __syncthreads();
#pragma unroll 8
    for (int k = 0; k < 32; k++) {
      ulonglong2 wA = *(const ulonglong2*)&W2[k][oq * 4];
      ulonglong2 wB = *(const ulonglong2*)&W2[k][oq * 4 + 2];
      ulonglong2 xv = *(const ulonglong2*)&Xsh[k][sl0];
      acc[0][0] = fma2(wA.x, xv.x, acc[0][0]); acc[0][1] = fma2(wA.x, xv.y, acc[0][1]);
      acc[1][0] = fma2(wA.y, xv.x, acc[1][0]); acc[1][1] = fma2(wA.y, xv.y, acc[1][1]);
      acc[2][0] = fma2(wB.x, xv.x, acc[2][0]); acc[2][1] = fma2(wB.x, xv.y, acc[2][1]);
      acc[3][0] = fma2(wB.y, xv.x, acc[3][0]); acc[3][1] = fma2(wB.y, xv.y, acc[3][1]);
    }
  }

  // Unpack + partial group stats (each thread's 4 channels lie in one group)
  float vals[4][4];
  float ls = 0.f, lq = 0.f;
#pragma unroll
  for (int i = 0; i < 4; i++) {
    float2 p0 = ull2f2(acc[i][0]);
    float2 p1 = ull2f2(acc[i][1]);
    vals[i][0] = p0.x; vals[i][1] = p0.y; vals[i][2] = p1.x; vals[i][3] = p1.y;
#pragma unroll
    for (int j = 0; j < 4; j++) { float v = vals[i][j]; ls += v; lq += v * v; }
  }
  redS[oq][sq] = ls;
  redQ[oq][sq] = lq;
  __syncthreads();
  if (tid < 16) {
    float s = 0.f, q = 0.f;
#pragma unroll
    for (int rme = 0; rme < 16; rme++) { s += redS[tid][rme]; q += redQ[tid][rme]; }
    g_part[proj][b][oTile * 16 + tid][sTile][0] = s;
    g_part[proj][b][oTile * 16 + tid][sTile][1] = q;
  }

  // Write y in patch layout [proj][b][o][n][p]
  const int t = s0 >> 12;
  const int yrow = (s0 >> 6) & 63;
  const int x0 = s0 & 63;
  const int hp = yrow >> 2, ph = yrow & 3, wp = x0 >> 2;
  const int n = (t << 8) + (hp << 4) + wp;
  const int p0 = ph << 2;
  const int o0 = oTile * 64 + oq * 4;
#pragma unroll
  for (int oi = 0; oi < 4; oi++) {
    float* dst = &g_y[proj][b][o0 + oi][n][p0];
    *(float4*)dst = make_float4(vals[oi][0], vals[oi][1], vals[oi][2], vals[oi][3]);
  }
}

// ---------------------------------------------------------------------------
// K2: finalize GN stats -> per-channel (scale, shift).
// ---------------------------------------------------------------------------
__global__ void __launch_bounds__(256) stats_kernel(
    const float* __restrict__ gqg, const float* __restrict__ gqb,
    const float* __restrict__ gkg, const float* __restrict__ gkb,
    const float* __restrict__ gvg, const float* __restrict__ gvb) {
  const int gid = blockIdx.x;
  const int proj = gid >> 6;
  const int rem = gid & 63;
  const int b = rem >> 5;
  const int g = rem & 31;
  const int tid = threadIdx.x;

  __shared__ float sS[256];
  __shared__ float sQ[256];
  sS[tid] = g_part[proj][b][g][tid][0];
  sQ[tid] = g_part[proj][b][g][tid][1];
  __syncthreads();
  for (int st = 128; st > 0; st >>= 1) {
    if (tid < st) { sS[tid] += sS[tid + st]; sQ[tid] += sQ[tid + st]; }
    __syncthreads();
  }
  __shared__ float mu_s, rstd_s;
  if (tid == 0) {
    float mu = sS[0] * (1.f / 65536.f);
    float var = sQ[0] * (1.f / 65536.f) - mu * mu;
    mu_s = mu;
    rstd_s = rsqrtf(var + EPS);
  }
  __syncthreads();
  if (tid < 4) {
    int o = g * 4 + tid;
    const float* gam = (proj == 0) ? gqg : ((proj == 1) ? gkg : gvg);
    const float* bet = (proj == 0) ? gqb : ((proj == 1) ? gkb : gvb);
    float sc = gam[o] * rstd_s;
    g_cscale[proj][b][o] = sc;
    g_cshift[proj][b][o] = bet[o] - mu_s * sc;
  }
}

// ---------------------------------------------------------------------------
// K3: pool q/k, apply GN affine, fold 1/sqrt(d) into q.
// ---------------------------------------------------------------------------
__global__ void __launch_bounds__(256) pool_kernel() {
  const int idx = blockIdx.x * 256 + threadIdx.x;
  const int n = idx & 1023;
  const int d = (idx >> 10) & 3;
  const int g = (idx >> 12) & 31;
  const int b = (idx >> 17) & 1;
  const int which = idx >> 18;
  const int o = g * 4 + d;
  const float4* src = (const float4*)&g_y[which][b][o][n][0];
  float sum = 0.f;
#pragma unroll
  for (int u = 0; u < 4; u++) { float4 v = src[u]; sum += v.x + v.y + v.z + v.w; }
  float val = g_cscale[which][b][o] * (sum * (1.f / 16.f)) + g_cshift[which][b][o];
  if (which == 0)
    g_qp[b][g][d][n] = val * 0.5f;
  else
    g_kp[b][g][d][n] = val;
}

// ---------------------------------------------------------------------------
// K4: fused attention. Block = (b,g, 128-row tile). m-tiles of 32.
// Phase A: warp wid -> rows wid*16..+15, lane = m; p duplicated {p,p} to wsh.
// Phase B: thread = 4 rows x 8 dp (4 f32x2 pairs), 2 m per iter.
// wsh stride 68 floats: 16B-aligned rows; rows i apart hit banks 4i mod 32
// so the 4 broadcast rows of a warp are conflict-free. vpsh columns
// bank-swizzled so each phase-B vp LDS.128 is one wavefront.
// ---------------------------------------------------------------------------
__global__ void __launch_bounds__(256, 3) attn_kernel(
    const float* __restrict__ rel_table, float* __restrict__ out) {
  const int bg = blockIdx.y;
  const int b = bg >> 5;
  const int g = bg & 31;
  const int nbase = blockIdx.x * 128;
  const int tid = threadIdx.x;
  const int wid = tid >> 5;
  const int lane = tid & 31;

  __shared__ float wsh[128][68];   // duplicated probs: [row][2*m (+pair)]
  __shared__ float vpsh[32][68];   // [m][swizzled dp col]
  __shared__ float qsh[128][4];
  __shared__ int   crsh[128];
  __shared__ float invsh[128];

  if (tid < 128) {
    int n = nbase + tid;
    float4 qv;
    qv.x = g_qp[b][g][0][n];
    qv.y = g_qp[b][g][1][n];
    qv.z = g_qp[b][g][2][n];
    qv.w = g_qp[b][g][3][n];
    *(float4*)qsh[tid] = qv;
    int t = n >> 8, y = (n >> 4) & 15, xx = n & 15;
    crsh[tid] = ((t + 3) * 31 + y + 15) * 31 + xx + 15;
  }

  // Shared thread decomposition for vp-fill and phase B
  const int rgrp = tid >> 3;               // 0..31 (also v-fill m row)
  const int dpg = tid & 7;                 // 0..7
  const int c0 = 8 * dpg + 4 * (dpg >> 2); // swizzled smem column
  const int r0 = rgrp * 4;                 // phase-B rows r0..r0+3

  // vp-fill constants
  const int o_f = g * 4 + (dpg >> 1);
  const int p0_f = (dpg & 1) * 8;
  const float vsc = g_cscale[2][b][o_f];
  const float vshf = g_cshift[2][b][o_f];
  const float* v_src = &g_y[2][b][o_f][0][p0_f];

  const float* __restrict__ tb = rel_table + g * TBL;
  const float* kp = &g_kp[b][g][0][0];

  ull acc[4][4];
#pragma unroll
  for (int i = 0; i < 4; i++)
#pragma unroll
    for (int j = 0; j < 4; j++) acc[i][j] = 0ull;
  float rs[16];
#pragma unroll
  for (int i = 0; i < 16; i++) rs[i] = 0.f;

  for (int mt = 0; mt < 32; mt++) {
    __syncthreads();

    // vp tile fill (GN affine folded), bank-swizzled columns
    {
      const float4* s = (const float4*)(v_src + (size_t)(mt * 32 + rgrp) * 16);
      float4 a = s[0], c = s[1];
      a.x = a.x * vsc + vshf; a.y = a.y * vsc + vshf; a.z = a.z * vsc + vshf; a.w = a.w * vsc + vshf;
      c.x = c.x * vsc + vshf; c.y = c.y * vsc + vshf; c.z = c.z * vsc + vshf; c.w = c.w * vsc + vshf;
      *(float4*)&vpsh[rgrp][c0] = a;
      *(float4*)&vpsh[rgrp][c0 + 4] = c;
    }

    // Phase A: lane = m, loop 16 rows
    {
      const int m = mt * 32 + lane;
      const float k0 = kp[m];
      const float k1 = kp[NN + m];
      const float k2 = kp[2 * NN + m];
      const float k3 = kp[3 * NN + m];
      const int tm = m >> 8, ym = (m >> 4) & 15, xm = m & 15;
      const int cm = (tm * 31 + ym) * 31 + xm;
#pragma unroll
      for (int i = 0; i < 16; i++) {
        int r = wid * 16 + i;
        float4 q = *(const float4*)qsh[r];
        float lg = q.x * k0 + q.y * k1 + q.z * k2 + q.w * k3;
        float p = __expf(lg + __ldg(tb + (crsh[r] - cm)));
        rs[i] += p;
        *(float2*)&wsh[r][2 * lane] = make_float2(p, p);
      }
    }
    __syncthreads();

    // Phase B: 2 m per iteration, packed f32x2 FMA
#pragma unroll 4
    for (int mc = 0; mc < 16; mc++) {
      const int m0 = mc * 2;
      ull va[4], vb[4];
      {
        ulonglong2 t0 = *(const ulonglong2*)&vpsh[m0][c0];
        ulonglong2 t1 = *(const ulonglong2*)&vpsh[m0][c0 + 4];
        va[0] = t0.x; va[1] = t0.y; va[2] = t1.x; va[3] = t1.y;
        ulonglong2 t2 = *(const ulonglong2*)&vpsh[m0 + 1][c0];
        ulonglong2 t3 = *(const ulonglong2*)&vpsh[m0 + 1][c0 + 4];
        vb[0] = t2.x; vb[1] = t2.y; vb[2] = t3.x; vb[3] = t3.y;
      }
#pragma unroll
      for (int i = 0; i < 4; i++) {
        ulonglong2 w = *(const ulonglong2*)&wsh[r0 + i][4 * mc];
        acc[i][0] = fma2(w.x, va[0], acc[i][0]);
        acc[i][1] = fma2(w.x, va[1], acc[i][1]);
        acc[i][2] = fma2(w.x, va[2], acc[i][2]);
        acc[i][3] = fma2(w.x, va[3], acc[i][3]);
        acc[i][0] = fma2(w.y, vb[0], acc[i][0]);
        acc[i][1] = fma2(w.y, vb[1], acc[i][1]);
        acc[i][2] = fma2(w.y, vb[2], acc[i][2]);
        acc[i][3] = fma2(w.y, vb[3], acc[i][3]);
      }
    }
  }

  // Row-sum reduction (lane-partial over m) -> invsh
#pragma unroll
  for (int i = 0; i < 16; i++) {
    float s = rs[i];
    s += __shfl_xor_sync(0xffffffffu, s, 16);
    s += __shfl_xor_sync(0xffffffffu, s, 8);
    s += __shfl_xor_sync(0xffffffffu, s, 4);
    s += __shfl_xor_sync(0xffffffffu, s, 2);
    s += __shfl_xor_sync(0xffffffffu, s, 1);
    if (lane == 0) invsh[wid * 16 + i] = 1.f / s;
  }
  __syncthreads();

  // Epilogue: normalize + un-patch store. Thread covers dp = 8*dpg..+7
  const int dE = dpg >> 1;
  const int ph0 = (dpg & 1) * 2;           // pbase>>2
  float* obase = out + ((size_t)(b * NC + g * 4 + dE)) * NS;
#pragma unroll
  for (int i = 0; i < 4; i++) {
    int r = r0 + i;
    int n = nbase + r;
    float iv = invsh[r];
    float2 f0 = ull2f2(acc[i][0]);
    float2 f1 = ull2f2(acc[i][1]);
    float2 f2 = ull2f2(acc[i][2]);
    float2 f3 = ull2f2(acc[i][3]);
    int t = n >> 8, hp = (n >> 4) & 15, wp = n & 15;
    float* rowb = obase + t * 4096 + wp * 4;
    *(float4*)(rowb + (hp * 4 + ph0) * 64) =
        make_float4(f0.x * iv, f0.y * iv, f1.x * iv, f1.y * iv);
    *(float4*)(rowb + (hp * 4 + ph0 + 1) * 64) =
        make_float4(f2.x * iv, f2.y * iv, f3.x * iv, f3.y * iv);
  }
}

// ---------------------------------------------------------------------------
extern "C" void kernel_launch(void* const* d_in, const int* in_sizes, int n_in,
                              void* d_out, int out_size) {
  (void)in_sizes; (void)n_in; (void)out_size;
  const float* x   = (const float*)d_in[0];
  const float* Wq  = (const float*)d_in[1];
  const float* Wk  = (const float*)d_in[2];
  const float* Wv  = (const float*)d_in[3];
  const float* gqg = (const float*)d_in[4];
  const float* gqb = (const float*)d_in[5];
  const float* gkg = (const float*)d_in[6];
  const float* gkb = (const float*)d_in[7];
  const float* gvg = (const float*)d_in[8];
  const float* gvb = (const float*)d_in[9];
  const float* rel_table = (const float*)d_in[10];
  float* out = (float*)d_out;

  proj_kernel<<<dim3(256, 2, 6), 256>>>(x, Wq, Wk, Wv);
  stats_kernel<<<192, 256>>>(gqg, gqb, gkg, gkb, gvg, gvb);
  pool_kernel<<<2048, 256>>>();
  attn_kernel<<<dim3(8, 64), 256>>>(rel_table, out);
}

// round 6
// speedup vs baseline: 1.0846x; 1.0846x over previous
#include <cuda_runtime.h>

// Problem constants
#define NB 2
#define NC 128
#define NS 16384        // T*H*W = 4*64*64
#define NN 1024         // patch tokens: 4*16*16
#define NP 16           // pixels per patch
#define NG 32           // heads == groupnorm groups
#define TBL 6727        // (2T-1)*(2h-1)*(2w-1) = 7*31*31
#define EPS 1e-5f

typedef unsigned long long ull;
typedef unsigned int uint;

// Scratch (static device memory; no allocations)
__device__ float g_y[3][NB][NC][NN][NP];       // raw projections, patch layout (~50MB)
__device__ float g_part[3][NB][NG][256][2];    // per-sTile partial (sum, sumsq)
__device__ float g_cscale[3][NB][NC];          // GN folded: scale = gamma*rstd
__device__ float g_cshift[3][NB][NC];          // GN folded: shift = beta - mu*scale
__device__ float g_qp[NB][NG][4][NN];          // pooled normalized q (pre-scaled 1/sqrt(d))
__device__ float g_kp[NB][NG][4][NN];          // pooled normalized k

static __device__ __forceinline__ ull fma2(ull a, ull b, ull c) {
  ull d;
  asm("fma.rn.f32x2 %0, %1, %2, %3;" : "=l"(d) : "l"(a), "l"(b), "l"(c));
  return d;
}
static __device__ __forceinline__ float2 ull2f2(ull u) {
  float2 f;
  f.x = __uint_as_float((unsigned)u);
  f.y = __uint_as_float((unsigned)(u >> 32));
  return f;
}
static __device__ __forceinline__ uint tf32_rna(float x) {
  uint r;
  asm("cvt.rna.tf32.f32 %0, %1;" : "=r"(r) : "f"(x));
  return r;
}
// mma.sync m16n8k8 tf32: D += A*B (accumulate in place)
static __device__ __forceinline__ void mma_tf32(float* c, uint a0, uint a1,
                                                uint a2, uint a3, uint b0, uint b1) {
  asm("mma.sync.aligned.m16n8k8.row.col.f32.tf32.tf32.f32 "
      "{%0,%1,%2,%3}, {%4,%5,%6,%7}, {%8,%9}, {%0,%1,%2,%3};"
      : "+f"(c[0]), "+f"(c[1]), "+f"(c[2]), "+f"(c[3])
      : "r"(a0), "r"(a1), "r"(a2), "r"(a3), "r"(b0), "r"(b1));
}

// ---------------------------------------------------------------------------
// K1: projections with fma.rn.f32x2. Y[o,s] = sum_c W[o,c]*x[c,s].
// ---------------------------------------------------------------------------
__global__ void __launch_bounds__(256) proj_kernel(
    const float* __restrict__ x, const float* __restrict__ Wq,
    const float* __restrict__ Wk, const float* __restrict__ Wv) {
  const int sTile = blockIdx.x;
  const int oTile = blockIdx.y;
  const int proj = blockIdx.z >> 1;
  const int b = blockIdx.z & 1;
  const float* __restrict__ W = (proj == 0) ? Wq : ((proj == 1) ? Wk : Wv);

  __shared__ ull   W2[32][66];
  __shared__ float Xsh[32][64];
  __shared__ float redS[16][17];
  __shared__ float redQ[16][17];

  const int tid = threadIdx.x;
  const int oq = tid >> 4;
  const int sq = tid & 15;
  const int sl0 = sq * 4;
  const int s0 = sTile * 64 + sl0;

  ull acc[4][2];
#pragma unroll
  for (int i = 0; i < 4; i++) { acc[i][0] = 0ull; acc[i][1] = 0ull; }

  const float* __restrict__ xb = x + (size_t)b * NC * NS;

  for (int kc = 0; kc < 128; kc += 32) {
    __syncthreads();
#pragma unroll
    for (int i = tid; i < 2048; i += 256) {
      int ol = i >> 5, kk = i & 31;
      float w = W[(oTile * 64 + ol) * 128 + kc + kk];
      *(float2*)&W2[kk][ol] = make_float2(w, w);
    }
#pragma unroll
    for (int i = tid; i < 2048; i += 256) {
      int kk = i >> 6, ss = i & 63;
      Xsh[kk][ss] = xb[(size_t)(kc + kk) * NS + sTile * 64 + ss];
    }
    __syncthreads();
#pragma unroll 8
    for (int k = 0; k < 32; k++) {
      ulonglong2 wA = *(const ulonglong2*)&W2[k][oq * 4];
      ulonglong2 wB = *(const ulonglong2*)&W2[k][oq * 4 + 2];
      ulonglong2 xv = *(const ulonglong2*)&Xsh[k][sl0];
      acc[0][0] = fma2(wA.x, xv.x, acc[0][0]); acc[0][1] = fma2(wA.x, xv.y, acc[0][1]);
      acc[1][0] = fma2(wA.y, xv.x, acc[1][0]); acc[1][1] = fma2(wA.y, xv.y, acc[1][1]);
      acc[2][0] = fma2(wB.x, xv.x, acc[2][0]); acc[2][1] = fma2(wB.x, xv.y, acc[2][1]);
      acc[3][0] = fma2(wB.y, xv.x, acc[3][0]); acc[3][1] = fma2(wB.y, xv.y, acc[3][1]);
    }
  }

  float vals[4][4];
  float ls = 0.f, lq = 0.f;
#pragma unroll
  for (int i = 0; i < 4; i++) {
    float2 p0 = ull2f2(acc[i][0]);
    float2 p1 = ull2f2(acc[i][1]);
    vals[i][0] = p0.x; vals[i][1] = p0.y; vals[i][2] = p1.x; vals[i][3] = p1.y;
#pragma unroll
    for (int j = 0; j < 4; j++) { float v = vals[i][j]; ls += v; lq += v * v; }
  }
  redS[oq][sq] = ls;
  redQ[oq][sq] = lq;
  __syncthreads();
  if (tid < 16) {
    float s = 0.f, q = 0.f;
#pragma unroll
    for (int rme = 0; rme < 16; rme++) { s += redS[tid][rme]; q += redQ[tid][rme]; }
    g_part[proj][b][oTile * 16 + tid][sTile][0] = s;
    g_part[proj][b][oTile * 16 + tid][sTile][1] = q;
  }

  const int t = s0 >> 12;
  const int yrow = (s0 >> 6) & 63;
  const int x0 = s0 & 63;
  const int hp = yrow >> 2, ph = yrow & 3, wp = x0 >> 2;
  const int n = (t << 8) + (hp << 4) + wp;
  const int p0 = ph << 2;
  const int o0 = oTile * 64 + oq * 4;
#pragma unroll
  for (int oi = 0; oi < 4; oi++) {
    float* dst = &g_y[proj][b][o0 + oi][n][p0];
    *(float4*)dst = make_float4(vals[oi][0], vals[oi][1], vals[oi][2], vals[oi][3]);
  }
}

// ---------------------------------------------------------------------------
// K2: finalize GN stats -> per-channel (scale, shift).
// ---------------------------------------------------------------------------
__global__ void __launch_bounds__(256) stats_kernel(
    const float* __restrict__ gqg, const float* __restrict__ gqb,
    const float* __restrict__ gkg, const float* __restrict__ gkb,
    const float* __restrict__ gvg, const float* __restrict__ gvb) {
  const int gid = blockIdx.x;
  const int proj = gid >> 6;
  const int rem = gid & 63;
  const int b = rem >> 5;
  const int g = rem & 31;
  const int tid = threadIdx.x;

  __shared__ float sS[256];
  __shared__ float sQ[256];
  sS[tid] = g_part[proj][b][g][tid][0];
  sQ[tid] = g_part[proj][b][g][tid][1];
  __syncthreads();
  for (int st = 128; st > 0; st >>= 1) {
    if (tid < st) { sS[tid] += sS[tid + st]; sQ[tid] += sQ[tid + st]; }
    __syncthreads();
  }
  __shared__ float mu_s, rstd_s;
  if (tid == 0) {
    float mu = sS[0] * (1.f / 65536.f);
    float var = sQ[0] * (1.f / 65536.f) - mu * mu;
    mu_s = mu;
    rstd_s = rsqrtf(var + EPS);
  }
  __syncthreads();
  if (tid < 4) {
    int o = g * 4 + tid;
    const float* gam = (proj == 0) ? gqg : ((proj == 1) ? gkg : gvg);
    const float* bet = (proj == 0) ? gqb : ((proj == 1) ? gkb : gvb);
    float sc = gam[o] * rstd_s;
    g_cscale[proj][b][o] = sc;
    g_cshift[proj][b][o] = bet[o] - mu_s * sc;
  }
}

// ---------------------------------------------------------------------------
// K3: pool q/k, apply GN affine, fold 1/sqrt(d) into q.
// ---------------------------------------------------------------------------
__global__ void __launch_bounds__(256) pool_kernel() {
  const int idx = blockIdx.x * 256 + threadIdx.x;
  const int n = idx & 1023;
  const int d = (idx >> 10) & 3;
  const int g = (idx >> 12) & 31;
  const int b = (idx >> 17) & 1;
  const int which = idx >> 18;
  const int o = g * 4 + d;
  const float4* src = (const float4*)&g_y[which][b][o][n][0];
  float sum = 0.f;
#pragma unroll
  for (int u = 0; u < 4; u++) { float4 v = src[u]; sum += v.x + v.y + v.z + v.w; }
  float val = g_cscale[which][b][o] * (sum * (1.f / 16.f)) + g_cshift[which][b][o];
  if (which == 0)
    g_qp[b][g][d][n] = val * 0.5f;
  else
    g_kp[b][g][d][n] = val;
}

// ---------------------------------------------------------------------------
// K4: fused attention, AV on tensor pipe (mma.sync m16n8k8 tf32, 3-way split).
// Block = (b,g, 128-row tile), 8 warps. m-tiles of 32 (4 k-steps of 8).
// Phase A (as R2): warp wid owns rows wid*16..+15, lane = m. P split into
//   tf32 hi + tf32 lo, stored scalar with k-interleaved column permutation
//   pos(c) = (c>>3)*8 + (c&3)*2 + ((c>>2)&1)  so an A-fragment pair
//   {A[r][ks*8+tc], A[r][ks*8+tc+4]} is one LDS.64.
// V tile filled as [m][dp] hi/lo copies (GN affine folded, split at fill).
// Phase B: warp owns the same 16 rows x all 64 dp; acc 8 dptiles x 4 regs.
//   Per (kstep): load A hi/lo frags (4 LDS.64); per dptile: 4 LDS.32 B + 3 mma.
// Softmax denominators kept in registers; full-warp reduced at end.
// ---------------------------------------------------------------------------
// dynamic smem layout (floats):
#define WSH_STRIDE 36
#define OFF_WH   0                       // [128][36] P hi
#define OFF_WL   (OFF_WH + 128*WSH_STRIDE)
#define OFF_VH   (OFF_WL + 128*WSH_STRIDE) // [32][68] V hi
#define OFF_VL   (OFF_VH + 32*68)
#define OFF_Q    (OFF_VL + 32*68)        // [128][4]
#define OFF_CR   (OFF_Q + 128*4)         // [128] int
#define OFF_INV  (OFF_CR + 128)          // [128]
#define SMEM_FLOATS (OFF_INV + 128)

__global__ void __launch_bounds__(256) attn_kernel(
    const float* __restrict__ rel_table, float* __restrict__ out) {
  extern __shared__ float smf[];
  float* wshH = smf + OFF_WH;
  float* wshL = smf + OFF_WL;
  float* vpH  = smf + OFF_VH;
  float* vpL  = smf + OFF_VL;
  float* qsh  = smf + OFF_Q;
  int*   crsh = (int*)(smf + OFF_CR);
  float* invsh = smf + OFF_INV;

  const int bg = blockIdx.y;
  const int b = bg >> 5;
  const int g = bg & 31;
  const int nbase = blockIdx.x * 128;
  const int tid = threadIdx.x;
  const int wid = tid >> 5;
  const int lane = tid & 31;

  if (tid < 128) {
    int n = nbase + tid;
    float4 qv;
    qv.x = g_qp[b][g][0][n];
    qv.y = g_qp[b][g][1][n];
    qv.z = g_qp[b][g][2][n];
    qv.w = g_qp[b][g][3][n];
    *(float4*)&qsh[tid * 4] = qv;
    int t = n >> 8, y = (n >> 4) & 15, xx = n & 15;
    crsh[tid] = ((t + 3) * 31 + y + 15) * 31 + xx + 15;
  }

  // vp-fill constants: thread handles one (m row, 8-dp segment)
  const int v_ml = tid >> 3;               // 0..31
  const int seg = tid & 7;                 // 0..7
  const int v_dp0 = seg * 8;
  const int o_f = g * 4 + (seg >> 1);
  const int p0_f = (seg & 1) * 8;
  const float vsc = g_cscale[2][b][o_f];
  const float vshf = g_cshift[2][b][o_f];
  const float* v_src = &g_y[2][b][o_f][0][p0_f];

  const float* __restrict__ tb = rel_table + g * TBL;
  const float* kp = &g_kp[b][g][0][0];

  // phase A column permutation
  const int pcol = ((lane >> 3) << 3) + ((lane & 3) << 1) + ((lane >> 2) & 1);

  // phase B fragment coords
  const int gr = lane >> 2;                // 0..7
  const int tc = lane & 3;                 // 0..3
  const int rA = wid * 16 + gr;            // A-frag rows rA, rA+8

  float acc[8][4];
#pragma unroll
  for (int i = 0; i < 8; i++)
#pragma unroll
    for (int j = 0; j < 4; j++) acc[i][j] = 0.f;
  float rs[16];
#pragma unroll
  for (int i = 0; i < 16; i++) rs[i] = 0.f;

  for (int mt = 0; mt < 32; mt++) {
    __syncthreads();

    // V tile fill: hi/lo tf32 split, GN affine folded. layout [m][dp], stride 68
    {
      const float4* s = (const float4*)(v_src + (size_t)(mt * 32 + v_ml) * 16);
      float4 a = s[0], c = s[1];
      float v[8];
      v[0] = a.x * vsc + vshf; v[1] = a.y * vsc + vshf;
      v[2] = a.z * vsc + vshf; v[3] = a.w * vsc + vshf;
      v[4] = c.x * vsc + vshf; v[5] = c.y * vsc + vshf;
      v[6] = c.z * vsc + vshf; v[7] = c.w * vsc + vshf;
      float hi[8], lo[8];
#pragma unroll
      for (int u = 0; u < 8; u++) {
        hi[u] = __uint_as_float(tf32_rna(v[u]));
        lo[u] = __uint_as_float(tf32_rna(v[u] - hi[u]));
      }
      float* dH = &vpH[v_ml * 68 + v_dp0];
      float* dL = &vpL[v_ml * 68 + v_dp0];
      *(float4*)dH = make_float4(hi[0], hi[1], hi[2], hi[3]);
      *(float4*)(dH + 4) = make_float4(hi[4], hi[5], hi[6], hi[7]);
      *(float4*)dL = make_float4(lo[0], lo[1], lo[2], lo[3]);
      *(float4*)(dL + 4) = make_float4(lo[4], lo[5], lo[6], lo[7]);
    }

    // Phase A: lane = m, 16 rows; store tf32 hi/lo scalars at permuted col
    {
      const int m = mt * 32 + lane;
      const float k0 = kp[m];
      const float k1 = kp[NN + m];
      const float k2 = kp[2 * NN + m];
      const float k3 = kp[3 * NN + m];
      const int tm = m >> 8, ym = (m >> 4) & 15, xm = m & 15;
      const int cm = (tm * 31 + ym) * 31 + xm;
#pragma unroll
      for (int i = 0; i < 16; i++) {
        int r = wid * 16 + i;
        float4 q = *(const float4*)&qsh[r * 4];
        float lg = q.x * k0 + q.y * k1 + q.z * k2 + q.w * k3;
        float p = __expf(lg + __ldg(tb + (crsh[r] - cm)));
        rs[i] += p;
        float hif = __uint_as_float(tf32_rna(p));
        float lof = __uint_as_float(tf32_rna(p - hif));
        wshH[r * WSH_STRIDE + pcol] = hif;
        wshL[r * WSH_STRIDE + pcol] = lof;
      }
    }
    __syncthreads();

    // Phase B: tensor-core AV
#pragma unroll
    for (int ks = 0; ks < 4; ks++) {
      const int ca = ks * 8 + tc * 2;
      float2 ah0 = *(const float2*)&wshH[rA * WSH_STRIDE + ca];        // {a0,a2}h
      float2 ah1 = *(const float2*)&wshH[(rA + 8) * WSH_STRIDE + ca];  // {a1,a3}h
      float2 al0 = *(const float2*)&wshL[rA * WSH_STRIDE + ca];
      float2 al1 = *(const float2*)&wshL[(rA + 8) * WSH_STRIDE + ca];
      uint a0h = __float_as_uint(ah0.x), a2h = __float_as_uint(ah0.y);
      uint a1h = __float_as_uint(ah1.x), a3h = __float_as_uint(ah1.y);
      uint a0l = __float_as_uint(al0.x), a2l = __float_as_uint(al0.y);
      uint a1l = __float_as_uint(al1.x), a3l = __float_as_uint(al1.y);
      const int rowk0 = (ks * 8 + tc) * 68;
      const int rowk1 = (ks * 8 + tc + 4) * 68;
#pragma unroll
      for (int dt = 0; dt < 8; dt++) {
        const int dpc = dt * 8 + gr;
        uint b0h = __float_as_uint(vpH[rowk0 + dpc]);
        uint b1h = __float_as_uint(vpH[rowk1 + dpc]);
        uint b0l = __float_as_uint(vpL[rowk0 + dpc]);
        uint b1l = __float_as_uint(vpL[rowk1 + dpc]);
        mma_tf32(acc[dt], a0h, a1h, a2h, a3h, b0h, b1h);
        mma_tf32(acc[dt], a0h, a1h, a2h, a3h, b0l, b1l);
        mma_tf32(acc[dt], a0l, a1l, a2l, a3l, b0h, b1h);
      }
    }
  }

  // Row-sum full-warp reduction; predicated writes avoid dynamic reg indexing
#pragma unroll
  for (int i = 0; i < 16; i++) {
    float s = rs[i];
    s += __shfl_xor_sync(0xffffffffu, s, 16);
    s += __shfl_xor_sync(0xffffffffu, s, 8);
    s += __shfl_xor_sync(0xffffffffu, s, 4);
    s += __shfl_xor_sync(0xffffffffu, s, 2);
    s += __shfl_xor_sync(0xffffffffu, s, 1);
    if (lane == i) invsh[wid * 16 + i] = 1.f / s;
  }
  __syncwarp();

  // Epilogue: normalize + un-patch store
  const float iv0 = invsh[rA];
  const float iv1 = invsh[rA + 8];
  {
    int n0 = nbase + rA;
    int n1 = n0 + 8;
    int t0 = n0 >> 8, hp0 = (n0 >> 4) & 15, wp0 = n0 & 15;
    int t1 = n1 >> 8, hp1 = (n1 >> 4) & 15, wp1 = n1 & 15;
    float* ob = out + (size_t)(b * NC + g * 4) * NS;
    long base0 = t0 * 4096 + hp0 * 256 + wp0 * 4;
    long base1 = t1 * 4096 + hp1 * 256 + wp1 * 4;
#pragma unroll
    for (int dt = 0; dt < 8; dt++) {
      int dp = dt * 8 + tc * 2;
      int d = dp >> 4;
      int ph = (dp & 15) >> 2;
      int pw = dp & 3;
      long coff = (long)d * NS + ph * 64 + pw;
      *(float2*)(ob + coff + base0) = make_float2(acc[dt][0] * iv0, acc[dt][1] * iv0);
      *(float2*)(ob + coff + base1) = make_float2(acc[dt][2] * iv1, acc[dt][3] * iv1);
    }
  }
}

// ---------------------------------------------------------------------------
extern "C" void kernel_launch(void* const* d_in, const int* in_sizes, int n_in,
                              void* d_out, int out_size) {
  (void)in_sizes; (void)n_in; (void)out_size;
  const float* x   = (const float*)d_in[0];
  const float* Wq  = (const float*)d_in[1];
  const float* Wk  = (const float*)d_in[2];
  const float* Wv  = (const float*)d_in[3];
  const float* gqg = (const float*)d_in[4];
  const float* gqb = (const float*)d_in[5];
  const float* gkg = (const float*)d_in[6];
  const float* gkb = (const float*)d_in[7];
  const float* gvg = (const float*)d_in[8];
  const float* gvb = (const float*)d_in[9];
  const float* rel_table = (const float*)d_in[10];
  float* out = (float*)d_out;

  static int smem_set = 0;
  const int smem_bytes = SMEM_FLOATS * 4;
  if (!smem_set) {
    cudaFuncSetAttribute(attn_kernel, cudaFuncAttributeMaxDynamicSharedMemorySize,
                         smem_bytes);
    smem_set = 1;
  }

  proj_kernel<<<dim3(256, 2, 6), 256>>>(x, Wq, Wk, Wv);
  stats_kernel<<<192, 256>>>(gqg, gqb, gkg, gkb, gvg, gvb);
  pool_kernel<<<2048, 256>>>();
  attn_kernel<<<dim3(8, 64), 256, smem_bytes>>>(rel_table, out);
}

// round 9
// speedup vs baseline: 1.2280x; 1.1323x over previous
#include <cuda_runtime.h>

// Problem constants
#define NB 2
#define NC 128
#define NS 16384        // T*H*W = 4*64*64
#define NN 1024         // patch tokens: 4*16*16
#define NP 16           // pixels per patch
#define NG 32           // heads == groupnorm groups
#define TBL 6727        // (2T-1)*(2h-1)*(2w-1) = 7*31*31
#define EPS 1e-5f
#define LOG2E 1.44269504088896f

typedef unsigned long long ull;
typedef unsigned int uint;

// Scratch (static device memory; no allocations)
__device__ float g_y[3][NB][NC][NN][NP];       // raw projections, patch layout (~50MB)
__device__ float g_part[3][NB][NG][256][2];    // per-sTile partial (sum, sumsq)
__device__ float g_cscale[3][NB][NC];          // GN folded: scale = gamma*rstd
__device__ float g_cshift[3][NB][NC];          // GN folded: shift = beta - mu*scale
__device__ float g_qp[NB][NG][4][NN];          // pooled q (x 0.5*log2e folded)
__device__ float g_kp[NB][NG][4][NN];          // pooled normalized k
__device__ float g_vh[NB][NG][NN][64];         // V hi tf32 plane (GN folded)
__device__ float g_vl[NB][NG][NN][64];         // V lo tf32 plane
__device__ float g_tb2[NG][TBL];               // rel_table * log2e

static __device__ __forceinline__ ull fma2(ull a, ull b, ull c) {
  ull d;
  asm("fma.rn.f32x2 %0, %1, %2, %3;" : "=l"(d) : "l"(a), "l"(b), "l"(c));
  return d;
}
static __device__ __forceinline__ float2 ull2f2(ull u) {
  float2 f;
  f.x = __uint_as_float((unsigned)u);
  f.y = __uint_as_float((unsigned)(u >> 32));
  return f;
}
static __device__ __forceinline__ uint tf32_rna(float x) {
  uint r;
  asm("cvt.rna.tf32.f32 %0, %1;" : "=r"(r) : "f"(x));
  return r;
}
static __device__ __forceinline__ float ex2f(float x) {
  float r;
  asm("ex2.approx.f32 %0, %1;" : "=f"(r) : "f"(x));
  return r;
}
// mma.sync m16n8k8 tf32: D += A*B (accumulate in place)
static __device__ __forceinline__ void mma_tf32(float* c, uint a0, uint a1,
                                                uint a2, uint a3, uint b0, uint b1) {
  asm("mma.sync.aligned.m16n8k8.row.col.f32.tf32.tf32.f32 "
      "{%0,%1,%2,%3}, {%4,%5,%6,%7}, {%8,%9}, {%0,%1,%2,%3};"
      : "+f"(c[0]), "+f"(c[1]), "+f"(c[2]), "+f"(c[3])
      : "r"(a0), "r"(a1), "r"(a2), "r"(a3), "r"(b0), "r"(b1));
}

// ---------------------------------------------------------------------------
// K1: projections with fma.rn.f32x2. Y[o,s] = sum_c W[o,c]*x[c,s].
// ---------------------------------------------------------------------------
__global__ void __launch_bounds__(256) proj_kernel(
    const float* __restrict__ x, const float* __restrict__ Wq,
    const float* __restrict__ Wk, const float* __restrict__ Wv) {
  const int sTile = blockIdx.x;
  const int oTile = blockIdx.y;
  const int proj = blockIdx.z >> 1;
  const int b = blockIdx.z & 1;
  const float* __restrict__ W = (proj == 0) ? Wq : ((proj == 1) ? Wk : Wv);

  __shared__ ull   W2[32][66];
  __shared__ float Xsh[32][64];
  __shared__ float redS[16][17];
  __shared__ float redQ[16][17];

  const int tid = threadIdx.x;
  const int oq = tid >> 4;
  const int sq = tid & 15;
  const int sl0 = sq * 4;
  const int s0 = sTile * 64 + sl0;

  ull acc[4][2];
#pragma unroll
  for (int i = 0; i < 4; i++) { acc[i][0] = 0ull; acc[i][1] = 0ull; }

  const float* __restrict__ xb = x + (size_t)b * NC * NS;

  for (int kc = 0; kc < 128; kc += 32) {
    __syncthreads();
#pragma unroll
    for (int i = tid; i < 2048; i += 256) {
      int ol = i >> 5, kk = i & 31;
      float w = W[(oTile * 64 + ol) * 128 + kc + kk];
      *(float2*)&W2[kk][ol] = make_float2(w, w);
    }
#pragma unroll
    for (int i = tid; i < 2048; i += 256) {
      int kk = i >> 6, ss = i & 63;
      Xsh[kk][ss] = xb[(size_t)(kc + kk) * NS + sTile * 64 + ss];
    }
    __syncthreads();
#pragma unroll 8
    for (int k = 0; k < 32; k++) {
      ulonglong2 wA = *(const ulonglong2*)&W2[k][oq * 4];
      ulonglong2 wB = *(const ulonglong2*)&W2[k][oq * 4 + 2];
      ulonglong2 xv = *(const ulonglong2*)&Xsh[k][sl0];
      acc[0][0] = fma2(wA.x, xv.x, acc[0][0]); acc[0][1] = fma2(wA.x, xv.y, acc[0][1]);
      acc[1][0] = fma2(wA.y, xv.x, acc[1][0]); acc[1][1] = fma2(wA.y, xv.y, acc[1][1]);
      acc[2][0] = fma2(wB.x, xv.x, acc[2][0]); acc[2][1] = fma2(wB.x, xv.y, acc[2][1]);
      acc[3][0] = fma2(wB.y, xv.x, acc[3][0]); acc[3][1] = fma2(wB.y, xv.y, acc[3][1]);
    }
  }

  float vals[4][4];
  float ls = 0.f, lq = 0.f;
#pragma unroll
  for (int i = 0; i < 4; i++) {
    float2 p0 = ull2f2(acc[i][0]);
    float2 p1 = ull2f2(acc[i][1]);
    vals[i][0] = p0.x; vals[i][1] = p0.y; vals[i][2] = p1.x; vals[i][3] = p1.y;
#pragma unroll
    for (int j = 0; j < 4; j++) { float v = vals[i][j]; ls += v; lq += v * v; }
  }
  redS[oq][sq] = ls;
  redQ[oq][sq] = lq;
  __syncthreads();
  if (tid < 16) {
    float s = 0.f, q = 0.f;
#pragma unroll
    for (int rme = 0; rme < 16; rme++) { s += redS[tid][rme]; q += redQ[tid][rme]; }
    g_part[proj][b][oTile * 16 + tid][sTile][0] = s;
    g_part[proj][b][oTile * 16 + tid][sTile][1] = q;
  }

  const int t = s0 >> 12;
  const int yrow = (s0 >> 6) & 63;
  const int x0 = s0 & 63;
  const int hp = yrow >> 2, ph = yrow & 3, wp = x0 >> 2;
  const int n = (t << 8) + (hp << 4) + wp;
  const int p0 = ph << 2;
  const int o0 = oTile * 64 + oq * 4;
#pragma unroll
  for (int oi = 0; oi < 4; oi++) {
    float* dst = &g_y[proj][b][o0 + oi][n][p0];
    *(float4*)dst = make_float4(vals[oi][0], vals[oi][1], vals[oi][2], vals[oi][3]);
  }
}

// ---------------------------------------------------------------------------
// K2: finalize GN stats -> per-channel (scale, shift).
// ---------------------------------------------------------------------------
__global__ void __launch_bounds__(256) stats_kernel(
    const float* __restrict__ gqg, const float* __restrict__ gqb,
    const float* __restrict__ gkg, const float* __restrict__ gkb,
    const float* __restrict__ gvg, const float* __restrict__ gvb) {
  const int gid = blockIdx.x;
  const int proj = gid >> 6;
  const int rem = gid & 63;
  const int b = rem >> 5;
  const int g = rem & 31;
  const int tid = threadIdx.x;

  __shared__ float sS[256];
  __shared__ float sQ[256];
  sS[tid] = g_part[proj][b][g][tid][0];
  sQ[tid] = g_part[proj][b][g][tid][1];
  __syncthreads();
  for (int st = 128; st > 0; st >>= 1) {
    if (tid < st) { sS[tid] += sS[tid + st]; sQ[tid] += sQ[tid + st]; }
    __syncthreads();
  }
  __shared__ float mu_s, rstd_s;
  if (tid == 0) {
    float mu = sS[0] * (1.f / 65536.f);
    float var = sQ[0] * (1.f / 65536.f) - mu * mu;
    mu_s = mu;
    rstd_s = rsqrtf(var + EPS);
  }
  __syncthreads();
  if (tid < 4) {
    int o = g * 4 + tid;
    const float* gam = (proj == 0) ? gqg : ((proj == 1) ? gkg : gvg);
    const float* bet = (proj == 0) ? gqb : ((proj == 1) ? gkb : gvb);
    float sc = gam[o] * rstd_s;
    g_cscale[proj][b][o] = sc;
    g_cshift[proj][b][o] = bet[o] - mu_s * sc;
  }
}

// ---------------------------------------------------------------------------
// K3a: pool q/k, apply GN affine; q folded with 0.5*log2e (scale+exp2 prep).
// ---------------------------------------------------------------------------
__global__ void __launch_bounds__(256) pool_kernel() {
  const int idx = blockIdx.x * 256 + threadIdx.x;
  const int n = idx & 1023;
  const int d = (idx >> 10) & 3;
  const int g = (idx >> 12) & 31;
  const int b = (idx >> 17) & 1;
  const int which = idx >> 18;
  const int o = g * 4 + d;
  const float4* src = (const float4*)&g_y[which][b][o][n][0];
  float sum = 0.f;
#pragma unroll
  for (int u = 0; u < 4; u++) { float4 v = src[u]; sum += v.x + v.y + v.z + v.w; }
  float val = g_cscale[which][b][o] * (sum * (1.f / 16.f)) + g_cshift[which][b][o];
  if (which == 0)
    g_qp[b][g][d][n] = val * (0.5f * LOG2E);
  else
    g_kp[b][g][d][n] = val;
}

// ---------------------------------------------------------------------------
// K3b: split V into tf32 hi/lo planes [b][g][m][dp], GN affine folded.
// ---------------------------------------------------------------------------
__global__ void __launch_bounds__(256) vsplit_kernel() {
  const int idx = blockIdx.x * 256 + threadIdx.x;   // 524288
  const int seg = idx & 7;                          // 8-dp segment
  const int m = (idx >> 3) & 1023;
  const int g = (idx >> 13) & 31;
  const int b = idx >> 18;
  const int o = g * 4 + (seg >> 1);
  const int p0 = (seg & 1) * 8;
  const float sc = g_cscale[2][b][o];
  const float sh = g_cshift[2][b][o];
  const float4* s = (const float4*)&g_y[2][b][o][m][p0];
  float4 a = s[0], c = s[1];
  float v[8] = {a.x, a.y, a.z, a.w, c.x, c.y, c.z, c.w};
  float hi[8], lo[8];
#pragma unroll
  for (int u = 0; u < 8; u++) {
    float f = v[u] * sc + sh;
    hi[u] = __uint_as_float(tf32_rna(f));
    lo[u] = __uint_as_float(tf32_rna(f - hi[u]));
  }
  float* dH = &g_vh[b][g][m][seg * 8];
  float* dL = &g_vl[b][g][m][seg * 8];
  *(float4*)dH = make_float4(hi[0], hi[1], hi[2], hi[3]);
  *(float4*)(dH + 4) = make_float4(hi[4], hi[5], hi[6], hi[7]);
  *(float4*)dL = make_float4(lo[0], lo[1], lo[2], lo[3]);
  *(float4*)(dL + 4) = make_float4(lo[4], lo[5], lo[6], lo[7]);
}

// ---------------------------------------------------------------------------
// K3c: pre-scale relative-position table by log2e.
// ---------------------------------------------------------------------------
__global__ void __launch_bounds__(256) tbl_kernel(const float* __restrict__ rel_table) {
  const int idx = blockIdx.x * 256 + threadIdx.x;
  if (idx < NG * TBL) ((float*)g_tb2)[idx] = rel_table[idx] * LOG2E;
}

// ---------------------------------------------------------------------------
// K4: fused attention, AV on tensor pipe. Block = (b,g, 128 rows), 8 warps.
// Phase A: lane=m, rows serial; p=ex2(q.k + bias2) stored RAW fp32 (HW
//   truncates to tf32 consistently for numerator & ones-sum) at permuted col.
// Phase B: per warp 16 rows x 64 dp; 2 mma (Bh,Bl) per (ks,dt) + 1 ones-mma
//   per ks accumulating exact row sums in acc[8].
// ---------------------------------------------------------------------------
__global__ void __launch_bounds__(256, 3) attn_kernel(float* __restrict__ out) {
  __shared__ float wshH[128][36];
  __shared__ float vpH[32][68];
  __shared__ float vpL[32][68];
  __shared__ float qsh[128][4];

  const int bg = blockIdx.y;
  const int b = bg >> 5;
  const int g = bg & 31;
  const int nbase = blockIdx.x * 128;
  const int tid = threadIdx.x;
  const int wid = tid >> 5;
  const int lane = tid & 31;

  if (tid < 128) {
    int n = nbase + tid;
    float4 qv;
    qv.x = g_qp[b][g][0][n];
    qv.y = g_qp[b][g][1][n];
    qv.z = g_qp[b][g][2][n];
    qv.w = g_qp[b][g][3][n];
    *(float4*)qsh[tid] = qv;
  }

  // crbase for this warp's 16-row group (rows have consecutive xx = i)
  const int n0w = nbase + wid * 16;
  const int crbase = (((n0w >> 8) + 3) * 31 + ((n0w >> 4) & 15) + 15) * 31 + 15;

  // vp-fill thread mapping
  const int v_ml = tid >> 3;
  const int v_dp0 = (tid & 7) * 8;
  const float* vhsrc = &g_vh[b][g][0][v_dp0];
  const float* vlsrc = &g_vl[b][g][0][v_dp0];

  const float* __restrict__ tb2 = &g_tb2[g][0];
  const float* kp = &g_kp[b][g][0][0];

  // phase A column permutation
  const int pcol = ((lane >> 3) << 3) + ((lane & 3) << 1) + ((lane >> 2) & 1);

  // phase B fragment coords
  const int gr = lane >> 2;
  const int tc = lane & 3;
  const int rA = wid * 16 + gr;
  const uint ONEU = __float_as_uint(1.0f);

  float acc[9][4];
#pragma unroll
  for (int i = 0; i < 9; i++)
#pragma unroll
    for (int j = 0; j < 4; j++) acc[i][j] = 0.f;

  for (int mt = 0; mt < 32; mt++) {
    __syncthreads();

    // V tile fill: pure copies of precomputed hi/lo planes
    {
      const float4* sH = (const float4*)(vhsrc + (size_t)(mt * 32 + v_ml) * 64);
      const float4* sL = (const float4*)(vlsrc + (size_t)(mt * 32 + v_ml) * 64);
      float4 h0 = sH[0], h1 = sH[1];
      float4 l0 = sL[0], l1 = sL[1];
      *(float4*)&vpH[v_ml][v_dp0] = h0;
      *(float4*)&vpH[v_ml][v_dp0 + 4] = h1;
      *(float4*)&vpL[v_ml][v_dp0] = l0;
      *(float4*)&vpL[v_ml][v_dp0 + 4] = l1;
    }

    // Phase A: lane = m, 16 rows
    {
      const int m = mt * 32 + lane;
      const float k0 = kp[m];
      const float k1 = kp[NN + m];
      const float k2 = kp[2 * NN + m];
      const float k3 = kp[3 * NN + m];
      const int cm = ((m >> 8) * 31 + ((m >> 4) & 15)) * 31 + (m & 15);
      const float* bptr = tb2 + (crbase - cm);
#pragma unroll
      for (int i = 0; i < 16; i++) {
        int r = wid * 16 + i;
        float4 q = *(const float4*)qsh[r];
        float lg = q.x * k0 + q.y * k1 + q.z * k2 + q.w * k3;
        float p = ex2f(lg + __ldg(bptr + i));
        wshH[r][pcol] = p;
      }
    }
    __syncthreads();

    // Phase B: tensor-core AV + ones row-sum
#pragma unroll
    for (int ks = 0; ks < 4; ks++) {
      const int ca = ks * 8 + tc * 2;
      float2 ah0 = *(const float2*)&wshH[rA][ca];
      float2 ah1 = *(const float2*)&wshH[rA + 8][ca];
      uint a0 = __float_as_uint(ah0.x), a2 = __float_as_uint(ah0.y);
      uint a1 = __float_as_uint(ah1.x), a3 = __float_as_uint(ah1.y);
      mma_tf32(acc[8], a0, a1, a2, a3, ONEU, ONEU);
      const int rowk0 = ks * 8 + tc;
      const int rowk1 = rowk0 + 4;
#pragma unroll
      for (int dt = 0; dt < 8; dt++) {
        const int dpc = dt * 8 + gr;
        uint b0h = __float_as_uint(vpH[rowk0][dpc]);
        uint b1h = __float_as_uint(vpH[rowk1][dpc]);
        uint b0l = __float_as_uint(vpL[rowk0][dpc]);
        uint b1l = __float_as_uint(vpL[rowk1][dpc]);
        mma_tf32(acc[dt], a0, a1, a2, a3, b0h, b1h);
        mma_tf32(acc[dt], a0, a1, a2, a3, b0l, b1l);
      }
    }
  }

  // Epilogue: normalize by ones-tile row sums + un-patch store
  const float iv0 = 1.f / acc[8][0];
  const float iv1 = 1.f / acc[8][2];
  {
    int n0 = nbase + rA;
    int n1 = n0 + 8;
    int t0 = n0 >> 8, hp0 = (n0 >> 4) & 15, wp0 = n0 & 15;
    int t1 = n1 >> 8, hp1 = (n1 >> 4) & 15, wp1 = n1 & 15;
    float* ob = out + (size_t)(b * NC + g * 4) * NS;
    long base0 = t0 * 4096 + hp0 * 256 + wp0 * 4;
    long base1 = t1 * 4096 + hp1 * 256 + wp1 * 4;
#pragma unroll
    for (int dt = 0; dt < 8; dt++) {
      int dp = dt * 8 + tc * 2;
      int d = dp >> 4;
      int ph = (dp & 15) >> 2;
      int pw = dp & 3;
      long coff = (long)d * NS + ph * 64 + pw;
      *(float2*)(ob + coff + base0) = make_float2(acc[dt][0] * iv0, acc[dt][1] * iv0);
      *(float2*)(ob + coff + base1) = make_float2(acc[dt][2] * iv1, acc[dt][3] * iv1);
    }
  }
}

// ---------------------------------------------------------------------------
extern "C" void kernel_launch(void* const* d_in, const int* in_sizes, int n_in,
                              void* d_out, int out_size) {
  (void)in_sizes; (void)n_in; (void)out_size;
  const float* x   = (const float*)d_in[0];
  const float* Wq  = (const float*)d_in[1];
  const float* Wk  = (const float*)d_in[2];
  const float* Wv  = (const float*)d_in[3];
  const float* gqg = (const float*)d_in[4];
  const float* gqb = (const float*)d_in[5];
  const float* gkg = (const float*)d_in[6];
  const float* gkb = (const float*)d_in[7];
  const float* gvg = (const float*)d_in[8];
  const float* gvb = (const float*)d_in[9];
  const float* rel_table = (const float*)d_in[10];
  float* out = (float*)d_out;

  proj_kernel<<<dim3(256, 2, 6), 256>>>(x, Wq, Wk, Wv);
  stats_kernel<<<192, 256>>>(gqg, gqb, gkg, gkb, gvg, gvb);
  pool_kernel<<<2048, 256>>>();
  vsplit_kernel<<<2048, 256>>>();
  tbl_kernel<<<(NG * TBL + 255) / 256, 256>>>(rel_table);
  attn_kernel<<<dim3(8, 64), 256>>>(out);
}